// round 1
// baseline (speedup 1.0000x reference)
#include <cuda_runtime.h>
#include <cuda_bf16.h>

// Output: 8192 x 8192 fp32, zeros except diag(triggers * mask).
// Strategy: bulk zero-fill via cudaMemsetAsync (near-peak HBM write BW,
// graph-capturable as a memset node), then a tiny kernel writes the
// 8192 diagonal elements.

static constexpr int N = 8192;

__global__ void diag_kernel(const float* __restrict__ triggers,
                            const int* __restrict__ mask,
                            float* __restrict__ out) {
    int i = blockIdx.x * blockDim.x + threadIdx.x;
    if (i < N) {
        // out[i][i] = triggers[i] * (float)mask[i]
        out[(size_t)i * (size_t)(N + 1)] = triggers[i] * (float)mask[i];
    }
}

extern "C" void kernel_launch(void* const* d_in, const int* in_sizes, int n_in,
                              void* d_out, int out_size) {
    const float* triggers = (const float*)d_in[0];
    const int*   mask     = (const int*)d_in[1];
    float*       out      = (float*)d_out;

    // Zero the full 256 MiB output (poisoned to 0xAA by the harness).
    cudaMemsetAsync(d_out, 0, (size_t)N * (size_t)N * sizeof(float), 0);

    // Write the diagonal.
    diag_kernel<<<(N + 255) / 256, 256>>>(triggers, mask, out);
}

// round 2
// speedup vs baseline: 1.0483x; 1.0483x over previous
#include <cuda_runtime.h>
#include <cuda_bf16.h>

// Output: 8192 x 8192 fp32, zeros except diag(triggers * mask).
// Single fused kernel: warp-coalesced vectorized zero-fill; the thread that
// owns the diagonal element's address overwrites it after its zero stores
// (same thread + same address => program-order guarantees final value).

static constexpr int N = 8192;                 // row = 8192 floats = 32 KB
static constexpr int FLOATS_PER_WARP = 2048;   // quarter-row per warp
static constexpr int ITERS = 16;               // 16 x (32 lanes x 16B) = 2048 floats

__global__ void __launch_bounds__(256)
fill_diag_kernel(const float* __restrict__ triggers,
                 const int* __restrict__ mask,
                 float4* __restrict__ out4) {
    const unsigned tid  = blockIdx.x * blockDim.x + threadIdx.x;
    const unsigned warp = tid >> 5;
    const unsigned lane = tid & 31;

    // This warp's region: floats [startf, startf + 2048), float4s [start4, start4 + 512)
    const size_t startf = (size_t)warp * FLOATS_PER_WARP;
    const size_t start4 = startf >> 2;

    const float4 z = make_float4(0.f, 0.f, 0.f, 0.f);
    // Iteration i: lanes write float4 indices start4 + i*32 + lane
    // => each instruction is one contiguous, fully-coalesced 512B wavefront.
#pragma unroll
    for (int i = 0; i < ITERS; i++) {
        out4[start4 + (size_t)i * 32 + lane] = z;
    }

    // Diagonal fix-up. The warp's 2048 floats lie within one row (2048 | 8192).
    // Row r's diagonal element is at column r; it falls in this warp's range
    // iff d = r - c0 is in [0, 2048). The owning lane is ((d>>2) & 31), which
    // is exactly this thread's own address set => same-thread ordering.
    const unsigned r  = (unsigned)(startf >> 13);   // row (N = 2^13)
    const unsigned c0 = (unsigned)(startf & (N - 1));
    const unsigned d  = r - c0;                     // unsigned wrap => big if r < c0
    if (d < (unsigned)FLOATS_PER_WARP && ((d >> 2) & 31) == lane) {
        ((float*)out4)[startf + d] = triggers[r] * (float)mask[r];
    }
}

extern "C" void kernel_launch(void* const* d_in, const int* in_sizes, int n_in,
                              void* d_out, int out_size) {
    const float* triggers = (const float*)d_in[0];
    const int*   mask     = (const int*)d_in[1];
    float4*      out4     = (float4*)d_out;

    // Total floats = N*N = 67,108,864; per warp 2048 => 32768 warps
    // => 1,048,576 threads => 4096 blocks of 256.
    const int blocks = (int)(((size_t)N * N / FLOATS_PER_WARP * 32) / 256);
    fill_diag_kernel<<<blocks, 256>>>(triggers, mask, out4);
}

// round 3
// speedup vs baseline: 1.0654x; 1.0164x over previous
#include <cuda_runtime.h>
#include <cuda_bf16.h>

// Output: 8192 x 8192 fp32, zeros except diag(triggers * mask).
// Single fused kernel: warp-coalesced 256-bit (v8.f32) zero stores; the
// thread owning the diagonal element's address overwrites it afterwards
// (same thread + same address => program order gives the final value).

static constexpr int N = 8192;                 // row = 8192 floats = 32 KB
static constexpr int FLOATS_PER_WARP = 2048;   // quarter-row per warp
static constexpr int ITERS = 8;                // 8 x (32 lanes x 32B) = 2048 floats

__device__ __forceinline__ void stg256_zero(float* p) {
    // Blackwell 256-bit store: one STG.E.256 of eight zero floats.
    asm volatile("st.global.v8.f32 [%0], {%1,%1,%1,%1,%1,%1,%1,%1};"
                 :: "l"(p), "f"(0.0f) : "memory");
}

__global__ void __launch_bounds__(256)
fill_diag_kernel(const float* __restrict__ triggers,
                 const int* __restrict__ mask,
                 float* __restrict__ out) {
    const unsigned tid  = blockIdx.x * blockDim.x + threadIdx.x;
    const unsigned warp = tid >> 5;
    const unsigned lane = tid & 31;

    // This warp's region: floats [startf, startf + 2048)
    const size_t startf = (size_t)warp * FLOATS_PER_WARP;
    float* base = out + startf + (size_t)lane * 8;

    // Iteration i: lanes store 32 x 32B = 1024B contiguous per instruction.
#pragma unroll
    for (int i = 0; i < ITERS; i++) {
        stg256_zero(base + (size_t)i * 256);
    }

    // Diagonal fix-up. The warp's 2048 floats lie within one row (2048 | 8192).
    // Row r's diagonal element (column r) is in range iff d = r - c0 in
    // [0, 2048). Owning lane for float offset d is ((d>>3) & 31) — the same
    // thread that zeroed that address, so program order guarantees the result.
    const unsigned r  = (unsigned)(startf >> 13);   // row (N = 2^13)
    const unsigned c0 = (unsigned)(startf & (N - 1));
    const unsigned d  = r - c0;                     // unsigned wrap => large if r < c0
    if (d < (unsigned)FLOATS_PER_WARP && ((d >> 3) & 31) == lane) {
        out[startf + d] = triggers[r] * (float)mask[r];
    }
}

extern "C" void kernel_launch(void* const* d_in, const int* in_sizes, int n_in,
                              void* d_out, int out_size) {
    const float* triggers = (const float*)d_in[0];
    const int*   mask     = (const int*)d_in[1];
    float*       out      = (float*)d_out;

    // Total floats = N*N = 67,108,864; 2048 per warp => 32768 warps
    // => 4096 blocks of 256 threads.
    const int blocks = (int)(((size_t)N * N / FLOATS_PER_WARP * 32) / 256);
    fill_diag_kernel<<<blocks, 256>>>(triggers, mask, out);
}